// round 1
// baseline (speedup 1.0000x reference)
#include <cuda_runtime.h>
#include <math.h>

#define Bsz 256
#define Ssz 256
#define Esz 512
#define Hsz 1024

// ---------------- scratch (static device allocations, allowed) ----------------
__device__ float g_Gf[(size_t)65536 * 4096];   // 1 GB: fwd gate pre-activations x@Wx_f + b_f
__device__ float g_Gb[(size_t)65536 * 4096];   // 1 GB: bwd gate pre-activations x@Wx_b + b_b
__device__ float g_h[2][2][Bsz * Hsz];         // [dir][buf][b*H] hidden double-buffer
__device__ unsigned int g_count;               // grid barrier ticket counter

// ---------------- init: zero h buffers + barrier (every replay) ----------------
__global__ void init_kernel() {
    size_t n = (size_t)2 * 2 * Bsz * Hsz;
    float* p = &g_h[0][0][0];
    for (size_t i = (size_t)blockIdx.x * blockDim.x + threadIdx.x; i < n;
         i += (size_t)gridDim.x * blockDim.x)
        p[i] = 0.f;
    if (blockIdx.x == 0 && threadIdx.x == 0) g_count = 0u;
}

// ---------------- phase 1: G[m][n] = emb[tok(m)] @ Wx[:,n] + bias[n] ----------------
// m = s*256 + b (time-major), n in [0,8192): dir = n/4096
// block tile: 128 rows x 64 cols, K=512 in 16-chunks. thread tile 8x4 (16x16 threads)
__global__ void __launch_bounds__(256) phase1_kernel(
    const int* __restrict__ inputs, const float* __restrict__ emb,
    const float* __restrict__ Wxf, const float* __restrict__ bf,
    const float* __restrict__ Wxb, const float* __restrict__ bb)
{
    __shared__ float At[128][20];   // padded: float4 stores aligned, scalar reads
    __shared__ float Bt[16][68];    // padded: float4 ld/st aligned
    __shared__ int tok[128];

    int n0 = blockIdx.x * 64;
    int m0 = blockIdx.y * 128;
    int dir = n0 >> 12;
    int nloc = n0 & 4095;
    const float* Wx   = dir ? Wxb : Wxf;
    const float* bias = dir ? bb : bf;
    float* Gout       = dir ? g_Gb : g_Gf;

    int tid = threadIdx.x;
    if (tid < 128) {
        int m = m0 + tid;
        tok[tid] = inputs[(m & 255) * Ssz + (m >> 8)];   // inputs[b][s]
    }
    __syncthreads();

    int tr = tid >> 4;              // 0..15 -> rows tr*8..+8
    int tc = tid & 15;              // 0..15 -> cols tc*4..+4
    int ar = tid >> 1, ah = (tid & 1) * 8;        // A loader: row ar, 8 floats at ah
    int bk = tid >> 4, bc = (tid & 15) * 4;       // B loader
    const float* arow = emb + (size_t)tok[ar] * Esz + ah;

    float acc[8][4];
    #pragma unroll
    for (int i = 0; i < 8; i++)
        #pragma unroll
        for (int j = 0; j < 4; j++) acc[i][j] = 0.f;

    for (int k0 = 0; k0 < Esz; k0 += 16) {
        float4 a0 = *(const float4*)(arow + k0);
        float4 a1 = *(const float4*)(arow + k0 + 4);
        float4 bv = *(const float4*)(Wx + (size_t)(k0 + bk) * 4096 + nloc + bc);
        __syncthreads();
        *(float4*)&At[ar][ah]     = a0;
        *(float4*)&At[ar][ah + 4] = a1;
        *(float4*)&Bt[bk][bc]     = bv;
        __syncthreads();
        #pragma unroll
        for (int kk = 0; kk < 16; kk++) {
            float a[8];
            #pragma unroll
            for (int i = 0; i < 8; i++) a[i] = At[tr * 8 + i][kk];
            float4 b4 = *(const float4*)&Bt[kk][tc * 4];
            #pragma unroll
            for (int i = 0; i < 8; i++) {
                acc[i][0] += a[i] * b4.x;
                acc[i][1] += a[i] * b4.y;
                acc[i][2] += a[i] * b4.z;
                acc[i][3] += a[i] * b4.w;
            }
        }
    }
    float bz0 = bias[nloc + tc * 4 + 0], bz1 = bias[nloc + tc * 4 + 1];
    float bz2 = bias[nloc + tc * 4 + 2], bz3 = bias[nloc + tc * 4 + 3];
    #pragma unroll
    for (int i = 0; i < 8; i++) {
        int m = m0 + tr * 8 + i;
        float4 r;
        r.x = acc[i][0] + bz0; r.y = acc[i][1] + bz1;
        r.z = acc[i][2] + bz2; r.w = acc[i][3] + bz3;
        *(float4*)(Gout + (size_t)m * 4096 + nloc + tc * 4) = r;
    }
}

// ---------------- phase 2: persistent recurrence ----------------
__device__ __forceinline__ float sigf(float x) { return 1.f / (1.f + expf(-x)); }

// 128 blocks x 256 threads (single wave on 148 SMs -> hand-rolled barrier is safe).
// Block ci: dir = ci/64, owns h-columns [g0, g0+16), i.e. Wh cols {e*1024+g0+gi}.
// Per step: [256 x 64] = h[256 x 1024] @ Wh[:, cols]; tile cols ordered c = e*16+gi.
// Thread (tr 0..31, tc 0..7): rows tr*8..+8, gi pair {tc*2, tc*2+1}, all 4 gates.
// Cell state c lives in registers for all 256 steps.
__global__ void __launch_bounds__(256) phase2_kernel(
    const float* __restrict__ Whf, const float* __restrict__ Whb)
{
    __shared__ float At[256][20];   // h chunk [256 rows][kc=16], padded
    __shared__ float Bt[16][68];    // Wh chunk [kc][64 cols], padded

    int ci  = blockIdx.x;
    int dir = ci >> 6;
    int g0  = (ci & 63) * 16;
    const float* Wh = dir ? Whb : Whf;
    const float* G  = dir ? g_Gb : g_Gf;

    int tid = threadIdx.x;
    int tr = tid >> 3;      // 0..31
    int tc = tid & 7;       // 0..7

    // B loader: tid -> (kk, col quad); col quad stays inside one gate segment
    int bkk = tid >> 4;
    int bcq = (tid & 15) * 4;
    int be = bcq >> 4, bg = bcq & 15;
    const float* wbase = Wh + (size_t)bkk * 4096 + (size_t)be * 1024 + g0 + bg;

    float cst[8][2];
    #pragma unroll
    for (int i = 0; i < 8; i++) { cst[i][0] = 0.f; cst[i][1] = 0.f; }

    for (int t = 0; t < Ssz; t++) {
        const float* hin = g_h[dir][t & 1];
        float*       hout = g_h[dir][(t + 1) & 1];
        int s = dir ? (Ssz - 1 - t) : t;

        float acc[8][8];
        #pragma unroll
        for (int i = 0; i < 8; i++)
            #pragma unroll
            for (int j = 0; j < 8; j++) acc[i][j] = 0.f;

        for (int k0 = 0; k0 < Hsz; k0 += 16) {
            // h chunk: MUST bypass L1 (.cg) — written by other SMs this launch
            float4 av[4];
            #pragma unroll
            for (int l = 0; l < 4; l++) {
                int fidx = tid + l * 256;
                int row = fidx >> 2, q = fidx & 3;
                av[l] = __ldcg((const float4*)(hin + (size_t)row * Hsz + k0 + q * 4));
            }
            float4 bv = *(const float4*)(wbase + (size_t)k0 * 4096);
            __syncthreads();
            #pragma unroll
            for (int l = 0; l < 4; l++) {
                int fidx = tid + l * 256;
                int row = fidx >> 2, q = fidx & 3;
                *(float4*)&At[row][q * 4] = av[l];
            }
            *(float4*)&Bt[bkk][bcq] = bv;
            __syncthreads();
            #pragma unroll
            for (int kk = 0; kk < 16; kk++) {
                float a[8];
                #pragma unroll
                for (int i = 0; i < 8; i++) a[i] = At[tr * 8 + i][kk];
                #pragma unroll
                for (int e = 0; e < 4; e++) {
                    float2 b2 = *(const float2*)&Bt[kk][e * 16 + tc * 2];
                    #pragma unroll
                    for (int i = 0; i < 8; i++) {
                        acc[i][e * 2 + 0] += a[i] * b2.x;
                        acc[i][e * 2 + 1] += a[i] * b2.y;
                    }
                }
            }
        }

        // epilogue: add precomputed x@Wx+bias, gates, update c (regs), emit h
        #pragma unroll
        for (int i = 0; i < 8; i++) {
            int row = tr * 8 + i;
            const float* grow = G + ((size_t)(s * 256 + row)) * 4096 + g0 + tc * 2;
            float hv2[2];
            #pragma unroll
            for (int j = 0; j < 2; j++) {
                float gi_ = acc[i][0 + j] + grow[j];           // input gate
                float gf_ = acc[i][2 + j] + grow[j + 1024];    // forget gate
                float go_ = acc[i][4 + j] + grow[j + 2048];    // output gate
                float gc_ = acc[i][6 + j] + grow[j + 3072];    // candidate
                float cs = sigf(gf_) * cst[i][j] + sigf(gi_) * tanhf(gc_);
                cst[i][j] = cs;
                hv2[j] = sigf(go_) * tanhf(cs);
            }
            float2 st; st.x = hv2[0]; st.y = hv2[1];
            __stcg((float2*)(hout + (size_t)row * Hsz + g0 + tc * 2), st);
        }

        // grid barrier (monotonic ticket; reset by init_kernel each replay)
        __syncthreads();
        if (tid == 0) {
            __threadfence();
            unsigned int tk = atomicAdd(&g_count, 1u);
            unsigned int target = (tk / 128u + 1u) * 128u;
            while (*(volatile unsigned int*)&g_count < target) { }
            __threadfence();
        }
        __syncthreads();
    }
}

// ---------------- phase 3: head + softmax ----------------
__global__ void __launch_bounds__(256) phase3_kernel(
    const float* __restrict__ Whq, const float* __restrict__ bq, float* __restrict__ out)
{
    int b = blockIdx.x;
    const float* hf = g_h[0][0] + (size_t)b * Hsz;
    const float* hb = g_h[1][0] + (size_t)b * Hsz;
    float part[10];
    #pragma unroll
    for (int q = 0; q < 10; q++) part[q] = 0.f;
    for (int k = threadIdx.x; k < Hsz; k += 256) {
        float hv = hf[k] + hb[k];
        #pragma unroll
        for (int q = 0; q < 10; q++) part[q] += hv * Whq[k * 10 + q];
    }
    #pragma unroll
    for (int q = 0; q < 10; q++)
        #pragma unroll
        for (int off = 16; off > 0; off >>= 1)
            part[q] += __shfl_xor_sync(0xffffffffu, part[q], off);
    __shared__ float red[8][10];
    int w = threadIdx.x >> 5, lane = threadIdx.x & 31;
    if (lane == 0)
        for (int q = 0; q < 10; q++) red[w][q] = part[q];
    __syncthreads();
    if (threadIdx.x == 0) {
        float lg[10]; float mx = -1e30f;
        for (int q = 0; q < 10; q++) {
            float v = bq[q];
            for (int w2 = 0; w2 < 8; w2++) v += red[w2][q];
            lg[q] = v;
            mx = fmaxf(mx, v);
        }
        float ssum = 0.f;
        for (int q = 0; q < 10; q++) { lg[q] = expf(lg[q] - mx); ssum += lg[q]; }
        float inv = 1.f / ssum;
        for (int q = 0; q < 10; q++) out[b * 10 + q] = lg[q] * inv;
    }
}

// ---------------- launcher ----------------
extern "C" void kernel_launch(void* const* d_in, const int* in_sizes, int n_in,
                              void* d_out, int out_size)
{
    const int*   inputs = (const int*)d_in[0];
    const float* emb = (const float*)d_in[1];
    const float* Wxf = (const float*)d_in[2];
    const float* Whf = (const float*)d_in[3];
    const float* bf  = (const float*)d_in[4];
    const float* Wxb = (const float*)d_in[5];
    const float* Whb = (const float*)d_in[6];
    const float* bb  = (const float*)d_in[7];
    const float* Whq = (const float*)d_in[8];
    const float* bq  = (const float*)d_in[9];
    float* out = (float*)d_out;

    init_kernel<<<256, 256>>>();
    dim3 g1(128, 512);                       // N tiles (8192/64) x M tiles (65536/128)
    phase1_kernel<<<g1, 256>>>(inputs, emb, Wxf, bf, Wxb, bb);
    phase2_kernel<<<128, 256>>>(Whf, Whb);   // persistent, single wave
    phase3_kernel<<<256, 256>>>(Whq, bq, out);
}

// round 7
// speedup vs baseline: 3.4024x; 3.4024x over previous
#include <cuda_runtime.h>
#include <cuda_fp16.h>
#include <mma.h>
#include <math.h>
#include <stdint.h>

using namespace nvcuda;

#define Bsz 256
#define Ssz 256
#define Esz 512
#define Hsz 1024

// ======================= scratch =======================
__device__ float g_Gf[(size_t)65536 * 4096];            // fwd gate pre-acts (no bias)
__device__ float g_Gb[(size_t)65536 * 4096];            // bwd gate pre-acts (no bias)
__device__ __half g_hf16[2][2][Bsz * Hsz];              // [dir][buf] hidden, fp16
__device__ unsigned int g_count;                        // grid barrier
__device__ __half g_Xh[(size_t)65536 * 512];            // x fp16 (single)
__device__ __half g_Wxh[(size_t)512 * 8192];            // Wx hi, [k][dir*4096+n]
__device__ __half g_Wxl[(size_t)512 * 8192];            // Wx lo
__device__ __half g_Whh[(size_t)1024 * 8192];           // Wh hi, [k][dir*4096+n]
__device__ __half g_Whl[(size_t)1024 * 8192];           // Wh lo

// ======================= helpers =======================
__device__ __forceinline__ void cp_async16(void* sptr, const void* gptr) {
    uint32_t sa = (uint32_t)__cvta_generic_to_shared(sptr);
    asm volatile("cp.async.cg.shared.global [%0], [%1], 16;" :: "r"(sa), "l"(gptr) : "memory");
}
__device__ __forceinline__ void cp_commit() { asm volatile("cp.async.commit_group;" ::: "memory"); }
template <int N>
__device__ __forceinline__ void cp_wait() { asm volatile("cp.async.wait_group %0;" :: "n"(N) : "memory"); }

__device__ __forceinline__ float sigf(float x)   { return 1.f / (1.f + __expf(-x)); }
__device__ __forceinline__ float tanhf_(float x) { return 2.f / (1.f + __expf(-2.f * x)) - 1.f; }

// ======================= init =======================
__global__ void init_kernel() {
    size_t n = (size_t)2 * 2 * Bsz * Hsz;
    __half* p = &g_hf16[0][0][0];
    for (size_t i = (size_t)blockIdx.x * blockDim.x + threadIdx.x; i < n;
         i += (size_t)gridDim.x * blockDim.x)
        p[i] = __float2half(0.f);
    if (blockIdx.x == 0 && threadIdx.x == 0) g_count = 0u;
}

// ======================= split/prep kernels =======================
__global__ void __launch_bounds__(256) split_x_kernel(
    const int* __restrict__ inputs, const float* __restrict__ emb)
{
    size_t idx = (size_t)blockIdx.x * blockDim.x + threadIdx.x;
    if (idx >= (size_t)65536 * 512) return;
    int m = (int)(idx >> 9);
    int k = (int)(idx & 511);
    int b = m & 255, s = m >> 8;
    int tok = inputs[b * Ssz + s];
    g_Xh[idx] = __float2half(emb[(size_t)tok * Esz + k]);
}

__global__ void __launch_bounds__(256) split_wx_kernel(
    const float* __restrict__ Wxf, const float* __restrict__ Wxb)
{
    size_t idx = (size_t)blockIdx.x * blockDim.x + threadIdx.x;
    if (idx >= (size_t)512 * 8192) return;
    int k = (int)(idx >> 13);
    int c = (int)(idx & 8191);
    const float* W = (c >= 4096) ? Wxb : Wxf;
    float v = W[(size_t)k * 4096 + (c & 4095)];
    __half hi = __float2half(v);
    __half lo = __float2half(v - __half2float(hi));
    g_Wxh[idx] = hi;
    g_Wxl[idx] = lo;
}

__global__ void __launch_bounds__(256) split_wh_kernel(
    const float* __restrict__ Whf, const float* __restrict__ Whb)
{
    size_t idx = (size_t)blockIdx.x * blockDim.x + threadIdx.x;
    if (idx >= (size_t)1024 * 8192) return;
    int k = (int)(idx >> 13);
    int c = (int)(idx & 8191);
    const float* W = (c >= 4096) ? Whb : Whf;
    float v = W[(size_t)k * 4096 + (c & 4095)];
    __half hi = __float2half(v);
    __half lo = __float2half(v - __half2float(hi));
    g_Whh[idx] = hi;
    g_Whl[idx] = lo;
}

// ======================= phase 1: WMMA GEMM =======================
// G[65536,8192] = X_fp16[65536,512] @ (Whi + Wlo)[512,8192]
// CTA tile 128x64, K-chunks of 64, cp.async double-buffered.
// smem: A 2x[128][72] half (36864B) | Bh 2x[64][72] (18432B) | Bl (18432B)
#define P1_SMEM (36864 + 18432 + 18432)

__global__ void __launch_bounds__(256) phase1_mma_kernel()
{
    extern __shared__ char sm[];
    __half* sA  = (__half*)sm;                       // 2 x 128 x 72
    __half* sBh = (__half*)(sm + 36864);             // 2 x 64 x 72
    __half* sBl = (__half*)(sm + 55296);             // 2 x 64 x 72

    int tid = threadIdx.x;
    int wid = tid >> 5;
    int n0 = blockIdx.x * 64;       // global col in [0,8192)
    int m0 = blockIdx.y * 128;
    int wm = (wid & 3) * 32;
    int wn = (wid >> 2) * 32;

    wmma::fragment<wmma::accumulator, 16, 16, 16, float> acc[2][2];
    #pragma unroll
    for (int i = 0; i < 2; i++)
        #pragma unroll
        for (int j = 0; j < 2; j++) wmma::fill_fragment(acc[i][j], 0.f);

    // ---- prefetch helper (chunk kc into buffer b) ----
    auto prefetch = [&](int kc, int b) {
        __half* A = sA + b * 128 * 72;
        __half* Bh = sBh + b * 64 * 72;
        __half* Bl = sBl + b * 64 * 72;
        #pragma unroll
        for (int i = 0; i < 4; i++) {                 // A: 1024 16B units
            int u = tid + i * 256;
            int row = u >> 3, seg = u & 7;
            cp_async16(A + row * 72 + seg * 8,
                       g_Xh + (size_t)(m0 + row) * 512 + kc * 64 + seg * 8);
        }
        #pragma unroll
        for (int i = 0; i < 2; i++) {                 // B: 512 units each
            int u = tid + i * 256;
            int row = u >> 3, seg = u & 7;
            size_t gof = (size_t)(kc * 64 + row) * 8192 + n0 + seg * 8;
            cp_async16(Bh + row * 72 + seg * 8, g_Wxh + gof);
            cp_async16(Bl + row * 72 + seg * 8, g_Wxl + gof);
        }
        cp_commit();
    };

    prefetch(0, 0);
    for (int kc = 0; kc < 8; kc++) {
        int b = kc & 1;
        if (kc + 1 < 8) { prefetch(kc + 1, b ^ 1); cp_wait<1>(); }
        else cp_wait<0>();
        __syncthreads();
        __half* A = sA + b * 128 * 72;
        __half* Bh = sBh + b * 64 * 72;
        __half* Bl = sBl + b * 64 * 72;
        #pragma unroll
        for (int kk = 0; kk < 4; kk++) {
            wmma::fragment<wmma::matrix_a, 16, 16, 16, __half, wmma::row_major> af[2];
            wmma::fragment<wmma::matrix_b, 16, 16, 16, __half, wmma::row_major> bhf[2], blf[2];
            #pragma unroll
            for (int i = 0; i < 2; i++)
                wmma::load_matrix_sync(af[i], A + (wm + i * 16) * 72 + kk * 16, 72);
            #pragma unroll
            for (int j = 0; j < 2; j++) {
                wmma::load_matrix_sync(bhf[j], Bh + kk * 16 * 72 + wn + j * 16, 72);
                wmma::load_matrix_sync(blf[j], Bl + kk * 16 * 72 + wn + j * 16, 72);
            }
            #pragma unroll
            for (int i = 0; i < 2; i++)
                #pragma unroll
                for (int j = 0; j < 2; j++) {
                    wmma::mma_sync(acc[i][j], af[i], bhf[j], acc[i][j]);
                    wmma::mma_sync(acc[i][j], af[i], blf[j], acc[i][j]);
                }
        }
        __syncthreads();
    }

    // epilogue: store straight to G (bias applied in phase 2)
    int dir = n0 >> 12;
    int nl = n0 & 4095;
    float* Gout = dir ? g_Gb : g_Gf;
    #pragma unroll
    for (int i = 0; i < 2; i++)
        #pragma unroll
        for (int j = 0; j < 2; j++)
            wmma::store_matrix_sync(
                Gout + (size_t)(m0 + wm + i * 16) * 4096 + nl + wn + j * 16,
                acc[i][j], 4096, wmma::mem_row_major);
}

// ======================= phase 2: persistent WMMA recurrence =======================
// 128 CTAs x 256 thr. CTA ci: dir=ci>>6, h-cols [g0,g0+16), 64 gate-cols.
// Per step: acc[256x64] = h_fp16[256x1024] @ (Whi+Wlo)[1024, cols]; K-chunks 64, dbuf.
// smem: A 2x[256][72] half = 73728 (reused as f32 staging [256][68] = 69632)
//       Bh 2x[64][72] = 18432 @73728 | Bl @92160 -> total 110592
#define P2_SMEM (73728 + 18432 + 18432)

__global__ void __launch_bounds__(256, 1) phase2_kernel(
    const float* __restrict__ bf_, const float* __restrict__ bb_)
{
    extern __shared__ char sm[];
    __half* sA  = (__half*)sm;                        // 2 x 256 x 72
    __half* sBh = (__half*)(sm + 73728);
    __half* sBl = (__half*)(sm + 92160);
    float*  stg = (float*)sm;                         // staging [256][68]
    __shared__ float sBias[64];                       // c = e*16+j

    int ci  = blockIdx.x;
    int dir = ci >> 6;
    int g0  = (ci & 63) * 16;
    const float* G = dir ? g_Gb : g_Gf;
    const float* bias = dir ? bb_ : bf_;

    int tid = threadIdx.x;
    int wid = tid >> 5;
    int wm = (wid & 3) * 64;        // 4 x 64 rows
    int wn = (wid >> 2) * 32;       // 2 x 32 cols

    if (tid < 64) sBias[tid] = bias[(tid >> 4) * 1024 + g0 + (tid & 15)];

    float cst[16];
    #pragma unroll
    for (int j = 0; j < 16; j++) cst[j] = 0.f;

    __syncthreads();

    for (int t = 0; t < Ssz; t++) {
        const __half* hin = g_hf16[dir][t & 1];
        __half*       hout = g_hf16[dir][(t + 1) & 1];
        int s = dir ? (Ssz - 1 - t) : t;

        wmma::fragment<wmma::accumulator, 16, 16, 16, float> acc[4][2];
        #pragma unroll
        for (int i = 0; i < 4; i++)
            #pragma unroll
            for (int j = 0; j < 2; j++) wmma::fill_fragment(acc[i][j], 0.f);

        auto prefetch = [&](int kc, int b) {
            __half* A = sA + b * 256 * 72;
            __half* Bh = sBh + b * 64 * 72;
            __half* Bl = sBl + b * 64 * 72;
            #pragma unroll
            for (int i = 0; i < 8; i++) {             // A: 2048 units
                int u = tid + i * 256;
                int row = u >> 3, seg = u & 7;
                cp_async16(A + row * 72 + seg * 8,
                           hin + (size_t)row * 1024 + kc * 64 + seg * 8);
            }
            #pragma unroll
            for (int i = 0; i < 2; i++) {             // B: 512 units each (hi,lo)
                int u = tid + i * 256;
                int krow = u >> 3;
                int e = (u >> 1) & 3, h8 = u & 1;
                size_t gof = (size_t)(kc * 64 + krow) * 8192
                           + dir * 4096 + e * 1024 + g0 + h8 * 8;
                __half* sdst_h = Bh + krow * 72 + e * 16 + h8 * 8;
                __half* sdst_l = Bl + krow * 72 + e * 16 + h8 * 8;
                cp_async16(sdst_h, g_Whh + gof);
                cp_async16(sdst_l, g_Whl + gof);
            }
            cp_commit();
        };

        prefetch(0, 0);
        for (int kc = 0; kc < 16; kc++) {
            int b = kc & 1;
            if (kc + 1 < 16) { prefetch(kc + 1, b ^ 1); cp_wait<1>(); }
            else cp_wait<0>();
            __syncthreads();
            __half* A = sA + b * 256 * 72;
            __half* Bh = sBh + b * 64 * 72;
            __half* Bl = sBl + b * 64 * 72;
            #pragma unroll
            for (int kk = 0; kk < 4; kk++) {
                wmma::fragment<wmma::matrix_a, 16, 16, 16, __half, wmma::row_major> af[4];
                wmma::fragment<wmma::matrix_b, 16, 16, 16, __half, wmma::row_major> bhf[2], blf[2];
                #pragma unroll
                for (int i = 0; i < 4; i++)
                    wmma::load_matrix_sync(af[i], A + (wm + i * 16) * 72 + kk * 16, 72);
                #pragma unroll
                for (int j = 0; j < 2; j++) {
                    wmma::load_matrix_sync(bhf[j], Bh + kk * 16 * 72 + wn + j * 16, 72);
                    wmma::load_matrix_sync(blf[j], Bl + kk * 16 * 72 + wn + j * 16, 72);
                }
                #pragma unroll
                for (int i = 0; i < 4; i++)
                    #pragma unroll
                    for (int j = 0; j < 2; j++) {
                        wmma::mma_sync(acc[i][j], af[i], bhf[j], acc[i][j]);
                        wmma::mma_sync(acc[i][j], af[i], blf[j], acc[i][j]);
                    }
            }
            __syncthreads();
        }

        // stage accumulators to smem (f32, ld=68), aliases A buffers (synced above)
        #pragma unroll
        for (int i = 0; i < 4; i++)
            #pragma unroll
            for (int j = 0; j < 2; j++)
                wmma::store_matrix_sync(stg + (wm + i * 16) * 68 + wn + j * 16,
                                        acc[i][j], 68, wmma::mem_row_major);
        __syncthreads();

        // epilogue: thread tid owns batch-row tid, h-cols g0..g0+16
        {
            const float* grow = G + ((size_t)(s * 256 + tid)) * 4096 + g0;
            const float* srow = stg + tid * 68;
            union { __half h[16]; uint4 u[2]; } hv;
            #pragma unroll
            for (int j = 0; j < 16; j++) {
                float gi = srow[j]      + __ldg(grow + j)        + sBias[j];
                float gf = srow[16 + j] + __ldg(grow + 1024 + j) + sBias[16 + j];
                float go = srow[32 + j] + __ldg(grow + 2048 + j) + sBias[32 + j];
                float gc = srow[48 + j] + __ldg(grow + 3072 + j) + sBias[48 + j];
                float cs = sigf(gf) * cst[j] + sigf(gi) * tanhf_(gc);
                cst[j] = cs;
                hv.h[j] = __float2half(sigf(go) * tanhf_(cs));
            }
            uint4* dst = (uint4*)(hout + (size_t)tid * 1024 + g0);
            __stcg(dst, hv.u[0]);
            __stcg(dst + 1, hv.u[1]);
        }

        // grid barrier (monotonic ticket; reset each replay by init_kernel)
        __syncthreads();
        if (tid == 0) {
            __threadfence();
            unsigned int tk = atomicAdd(&g_count, 1u);
            unsigned int target = (tk / 128u + 1u) * 128u;
            while (*(volatile unsigned int*)&g_count < target) { }
            __threadfence();
        }
        __syncthreads();
    }
}

// ======================= phase 3: head + softmax =======================
__global__ void __launch_bounds__(256) phase3_kernel(
    const float* __restrict__ Whq, const float* __restrict__ bq, float* __restrict__ out)
{
    int b = blockIdx.x;
    const __half* hf = g_hf16[0][0] + (size_t)b * Hsz;
    const __half* hb = g_hf16[1][0] + (size_t)b * Hsz;
    float part[10];
    #pragma unroll
    for (int q = 0; q < 10; q++) part[q] = 0.f;
    for (int k = threadIdx.x; k < Hsz; k += 256) {
        float hv = __half2float(hf[k]) + __half2float(hb[k]);
        #pragma unroll
        for (int q = 0; q < 10; q++) part[q] += hv * Whq[k * 10 + q];
    }
    #pragma unroll
    for (int q = 0; q < 10; q++)
        #pragma unroll
        for (int off = 16; off > 0; off >>= 1)
            part[q] += __shfl_xor_sync(0xffffffffu, part[q], off);
    __shared__ float red[8][10];
    int w = threadIdx.x >> 5, lane = threadIdx.x & 31;
    if (lane == 0)
        for (int q = 0; q < 10; q++) red[w][q] = part[q];
    __syncthreads();
    if (threadIdx.x == 0) {
        float lg[10]; float mx = -1e30f;
        for (int q = 0; q < 10; q++) {
            float v = bq[q];
            for (int w2 = 0; w2 < 8; w2++) v += red[w2][q];
            lg[q] = v;
            mx = fmaxf(mx, v);
        }
        float ssum = 0.f;
        for (int q = 0; q < 10; q++) { lg[q] = expf(lg[q] - mx); ssum += lg[q]; }
        float inv = 1.f / ssum;
        for (int q = 0; q < 10; q++) out[b * 10 + q] = lg[q] * inv;
    }
}

// ======================= launcher =======================
extern "C" void kernel_launch(void* const* d_in, const int* in_sizes, int n_in,
                              void* d_out, int out_size)
{
    const int*   inputs = (const int*)d_in[0];
    const float* emb = (const float*)d_in[1];
    const float* Wxf = (const float*)d_in[2];
    const float* Whf = (const float*)d_in[3];
    const float* bf  = (const float*)d_in[4];
    const float* Wxb = (const float*)d_in[5];
    const float* Whb = (const float*)d_in[6];
    const float* bb  = (const float*)d_in[7];
    const float* Whq = (const float*)d_in[8];
    const float* bq  = (const float*)d_in[9];
    float* out = (float*)d_out;

    static int attr_set = 0;
    if (!attr_set) {
        cudaFuncSetAttribute(phase1_mma_kernel,
                             cudaFuncAttributeMaxDynamicSharedMemorySize, P1_SMEM);
        cudaFuncSetAttribute(phase2_kernel,
                             cudaFuncAttributeMaxDynamicSharedMemorySize, P2_SMEM);
        attr_set = 1;
    }

    init_kernel<<<256, 256>>>();
    split_x_kernel<<<131072, 256>>>(inputs, emb);
    split_wx_kernel<<<16384, 256>>>(Wxf, Wxb);
    split_wh_kernel<<<32768, 256>>>(Whf, Whb);
    dim3 g1(128, 512);                               // 8192/64 n-tiles x 65536/128 m-tiles
    phase1_mma_kernel<<<g1, 256, P1_SMEM>>>();
    phase2_kernel<<<128, 256, P2_SMEM>>>(bf, bb);    // persistent, single wave
    phase3_kernel<<<256, 256>>>(Whq, bq, out);
}

// round 12
// speedup vs baseline: 4.6751x; 1.3740x over previous
#include <cuda_runtime.h>
#include <cuda_fp16.h>
#include <mma.h>
#include <math.h>
#include <stdint.h>

using namespace nvcuda;

#define Bsz 256
#define Ssz 256
#define Esz 512
#define Hsz 1024

// ======================= scratch =======================
__device__ float g_Gf[(size_t)65536 * 4096];            // fwd gate pre-acts (no bias)
__device__ float g_Gb[(size_t)65536 * 4096];            // bwd gate pre-acts (no bias)
__device__ __half g_hf16[2][2][Bsz * Hsz];              // [dir][buf] hidden, fp16
__device__ unsigned int g_count;                        // grid barrier
__device__ __half g_Xh[(size_t)65536 * 512];            // x fp16
__device__ __half g_Wxh[(size_t)512 * 8192];            // Wx fp16, [k][dir*4096+n]
__device__ __half g_Whh[(size_t)1024 * 8192];           // Wh fp16, [k][dir*4096+n]

// ======================= helpers =======================
__device__ __forceinline__ void cp_async16(void* sptr, const void* gptr) {
    uint32_t sa = (uint32_t)__cvta_generic_to_shared(sptr);
    asm volatile("cp.async.cg.shared.global [%0], [%1], 16;" :: "r"(sa), "l"(gptr) : "memory");
}
__device__ __forceinline__ void cp_commit() { asm volatile("cp.async.commit_group;" ::: "memory"); }
template <int N>
__device__ __forceinline__ void cp_wait() { asm volatile("cp.async.wait_group %0;" :: "n"(N) : "memory"); }

__device__ __forceinline__ float sigf(float x)   { return 1.f / (1.f + __expf(-x)); }
__device__ __forceinline__ float tanhf_(float x) { return 2.f / (1.f + __expf(-2.f * x)) - 1.f; }

// ======================= init =======================
__global__ void init_kernel() {
    size_t n = (size_t)2 * 2 * Bsz * Hsz;
    __half* p = &g_hf16[0][0][0];
    for (size_t i = (size_t)blockIdx.x * blockDim.x + threadIdx.x; i < n;
         i += (size_t)gridDim.x * blockDim.x)
        p[i] = __float2half(0.f);
    if (blockIdx.x == 0 && threadIdx.x == 0) g_count = 0u;
}

// ======================= split/prep kernels =======================
__global__ void __launch_bounds__(256) split_x_kernel(
    const int* __restrict__ inputs, const float* __restrict__ emb)
{
    size_t idx = (size_t)blockIdx.x * blockDim.x + threadIdx.x;
    if (idx >= (size_t)65536 * 512) return;
    int m = (int)(idx >> 9);
    int k = (int)(idx & 511);
    int b = m & 255, s = m >> 8;
    int tok = inputs[b * Ssz + s];
    g_Xh[idx] = __float2half(emb[(size_t)tok * Esz + k]);
}

__global__ void __launch_bounds__(256) split_wx_kernel(
    const float* __restrict__ Wxf, const float* __restrict__ Wxb)
{
    size_t idx = (size_t)blockIdx.x * blockDim.x + threadIdx.x;
    if (idx >= (size_t)512 * 8192) return;
    int k = (int)(idx >> 13);
    int c = (int)(idx & 8191);
    const float* W = (c >= 4096) ? Wxb : Wxf;
    g_Wxh[idx] = __float2half(W[(size_t)k * 4096 + (c & 4095)]);
}

__global__ void __launch_bounds__(256) split_wh_kernel(
    const float* __restrict__ Whf, const float* __restrict__ Whb)
{
    size_t idx = (size_t)blockIdx.x * blockDim.x + threadIdx.x;
    if (idx >= (size_t)1024 * 8192) return;
    int k = (int)(idx >> 13);
    int c = (int)(idx & 8191);
    const float* W = (c >= 4096) ? Whb : Whf;
    g_Whh[idx] = __float2half(W[(size_t)k * 4096 + (c & 4095)]);
}

// ======================= phase 1: WMMA GEMM =======================
// G[65536,8192] = X_fp16[65536,512] @ W_fp16[512,8192]
// CTA tile 128x64, K-chunks of 64, cp.async double-buffered.
// smem: A 2x[128][72] half (36864B) | B 2x[64][72] (18432B)
#define P1_SMEM (36864 + 18432)

__global__ void __launch_bounds__(256) phase1_mma_kernel()
{
    extern __shared__ char sm[];
    __half* sA = (__half*)sm;                        // 2 x 128 x 72
    __half* sB = (__half*)(sm + 36864);              // 2 x 64 x 72

    int tid = threadIdx.x;
    int wid = tid >> 5;
    int n0 = blockIdx.x * 64;       // global col in [0,8192)
    int m0 = blockIdx.y * 128;
    int wm = (wid & 3) * 32;
    int wn = (wid >> 2) * 32;

    wmma::fragment<wmma::accumulator, 16, 16, 16, float> acc[2][2];
    #pragma unroll
    for (int i = 0; i < 2; i++)
        #pragma unroll
        for (int j = 0; j < 2; j++) wmma::fill_fragment(acc[i][j], 0.f);

    auto prefetch = [&](int kc, int b) {
        __half* A = sA + b * 128 * 72;
        __half* B = sB + b * 64 * 72;
        #pragma unroll
        for (int i = 0; i < 4; i++) {                 // A: 1024 16B units
            int u = tid + i * 256;
            int row = u >> 3, seg = u & 7;
            cp_async16(A + row * 72 + seg * 8,
                       g_Xh + (size_t)(m0 + row) * 512 + kc * 64 + seg * 8);
        }
        #pragma unroll
        for (int i = 0; i < 2; i++) {                 // B: 512 units
            int u = tid + i * 256;
            int row = u >> 3, seg = u & 7;
            cp_async16(B + row * 72 + seg * 8,
                       g_Wxh + (size_t)(kc * 64 + row) * 8192 + n0 + seg * 8);
        }
        cp_commit();
    };

    prefetch(0, 0);
    for (int kc = 0; kc < 8; kc++) {
        int b = kc & 1;
        if (kc + 1 < 8) { prefetch(kc + 1, b ^ 1); cp_wait<1>(); }
        else cp_wait<0>();
        __syncthreads();
        __half* A = sA + b * 128 * 72;
        __half* B = sB + b * 64 * 72;
        #pragma unroll
        for (int kk = 0; kk < 4; kk++) {
            wmma::fragment<wmma::matrix_a, 16, 16, 16, __half, wmma::row_major> af[2];
            wmma::fragment<wmma::matrix_b, 16, 16, 16, __half, wmma::row_major> bf2[2];
            #pragma unroll
            for (int i = 0; i < 2; i++)
                wmma::load_matrix_sync(af[i], A + (wm + i * 16) * 72 + kk * 16, 72);
            #pragma unroll
            for (int j = 0; j < 2; j++)
                wmma::load_matrix_sync(bf2[j], B + kk * 16 * 72 + wn + j * 16, 72);
            #pragma unroll
            for (int i = 0; i < 2; i++)
                #pragma unroll
                for (int j = 0; j < 2; j++)
                    wmma::mma_sync(acc[i][j], af[i], bf2[j], acc[i][j]);
        }
        __syncthreads();
    }

    // epilogue: store straight to G (bias applied in phase 2)
    int dir = n0 >> 12;
    int nl = n0 & 4095;
    float* Gout = dir ? g_Gb : g_Gf;
    #pragma unroll
    for (int i = 0; i < 2; i++)
        #pragma unroll
        for (int j = 0; j < 2; j++)
            wmma::store_matrix_sync(
                Gout + (size_t)(m0 + wm + i * 16) * 4096 + nl + wn + j * 16,
                acc[i][j], 4096, wmma::mem_row_major);
}

// ======================= phase 2: persistent WMMA recurrence =======================
// 128 CTAs x 256 thr. CTA ci: dir=ci>>6, h-cols [g0,g0+16), 64 gate-cols.
// Per step: acc[256x64] = h_fp16[256x1024] @ Wh_fp16[1024, cols]; K-chunks 64, dbuf.
// smem: A 2x[256][72] half = 73728 (reused as f32 staging [256][68])
//       B 2x[64][72] = 18432 @73728 -> total 92160
#define P2_SMEM (73728 + 18432)

__global__ void __launch_bounds__(256, 1) phase2_kernel(
    const float* __restrict__ bf_, const float* __restrict__ bb_)
{
    extern __shared__ char sm[];
    __half* sA = (__half*)sm;                         // 2 x 256 x 72
    __half* sB = (__half*)(sm + 73728);
    float*  stg = (float*)sm;                         // staging [256][68]
    __shared__ float sBias[64];                       // c = e*16+j

    int ci  = blockIdx.x;
    int dir = ci >> 6;
    int g0  = (ci & 63) * 16;
    const float* G = dir ? g_Gb : g_Gf;
    const float* bias = dir ? bb_ : bf_;

    int tid = threadIdx.x;
    int wid = tid >> 5;
    int wm = (wid & 3) * 64;        // 4 x 64 rows
    int wn = (wid >> 2) * 32;       // 2 x 32 cols

    if (tid < 64) sBias[tid] = bias[(tid >> 4) * 1024 + g0 + (tid & 15)];

    float cst[16];
    #pragma unroll
    for (int j = 0; j < 16; j++) cst[j] = 0.f;

    __syncthreads();

    for (int t = 0; t < Ssz; t++) {
        const __half* hin = g_hf16[dir][t & 1];
        __half*       hout = g_hf16[dir][(t + 1) & 1];
        int s = dir ? (Ssz - 1 - t) : t;

        wmma::fragment<wmma::accumulator, 16, 16, 16, float> acc[4][2];
        #pragma unroll
        for (int i = 0; i < 4; i++)
            #pragma unroll
            for (int j = 0; j < 2; j++) wmma::fill_fragment(acc[i][j], 0.f);

        auto prefetch = [&](int kc, int b) {
            __half* A = sA + b * 256 * 72;
            __half* B = sB + b * 64 * 72;
            #pragma unroll
            for (int i = 0; i < 8; i++) {             // A: 2048 units
                int u = tid + i * 256;
                int row = u >> 3, seg = u & 7;
                cp_async16(A + row * 72 + seg * 8,
                           hin + (size_t)row * 1024 + kc * 64 + seg * 8);
            }
            #pragma unroll
            for (int i = 0; i < 2; i++) {             // B: 512 units
                int u = tid + i * 256;
                int krow = u >> 3;
                int e = (u >> 1) & 3, h8 = u & 1;
                size_t gof = (size_t)(kc * 64 + krow) * 8192
                           + dir * 4096 + e * 1024 + g0 + h8 * 8;
                cp_async16(B + krow * 72 + e * 16 + h8 * 8, g_Whh + gof);
            }
            cp_commit();
        };

        prefetch(0, 0);
        for (int kc = 0; kc < 16; kc++) {
            int b = kc & 1;
            if (kc + 1 < 16) { prefetch(kc + 1, b ^ 1); cp_wait<1>(); }
            else cp_wait<0>();
            __syncthreads();
            __half* A = sA + b * 256 * 72;
            __half* B = sB + b * 64 * 72;
            #pragma unroll
            for (int kk = 0; kk < 4; kk++) {
                wmma::fragment<wmma::matrix_a, 16, 16, 16, __half, wmma::row_major> af[4];
                wmma::fragment<wmma::matrix_b, 16, 16, 16, __half, wmma::row_major> bf2[2];
                #pragma unroll
                for (int i = 0; i < 4; i++)
                    wmma::load_matrix_sync(af[i], A + (wm + i * 16) * 72 + kk * 16, 72);
                #pragma unroll
                for (int j = 0; j < 2; j++)
                    wmma::load_matrix_sync(bf2[j], B + kk * 16 * 72 + wn + j * 16, 72);
                #pragma unroll
                for (int i = 0; i < 4; i++)
                    #pragma unroll
                    for (int j = 0; j < 2; j++)
                        wmma::mma_sync(acc[i][j], af[i], bf2[j], acc[i][j]);
            }
            __syncthreads();
        }

        // stage accumulators to smem (f32, ld=68), aliases A buffers (synced above)
        #pragma unroll
        for (int i = 0; i < 4; i++)
            #pragma unroll
            for (int j = 0; j < 2; j++)
                wmma::store_matrix_sync(stg + (wm + i * 16) * 68 + wn + j * 16,
                                        acc[i][j], 68, wmma::mem_row_major);
        __syncthreads();

        // epilogue: thread tid owns batch-row tid, h-cols g0..g0+16
        {
            const float* grow = G + ((size_t)(s * 256 + tid)) * 4096 + g0;
            const float* srow = stg + tid * 68;
            union { __half h[16]; uint4 u[2]; } hv;
            #pragma unroll
            for (int j = 0; j < 16; j++) {
                float gi = srow[j]      + __ldg(grow + j)        + sBias[j];
                float gf = srow[16 + j] + __ldg(grow + 1024 + j) + sBias[16 + j];
                float go = srow[32 + j] + __ldg(grow + 2048 + j) + sBias[32 + j];
                float gc = srow[48 + j] + __ldg(grow + 3072 + j) + sBias[48 + j];
                float cs = sigf(gf) * cst[j] + sigf(gi) * tanhf_(gc);
                cst[j] = cs;
                hv.h[j] = __float2half(sigf(go) * tanhf_(cs));
            }
            uint4* dst = (uint4*)(hout + (size_t)tid * 1024 + g0);
            __stcg(dst, hv.u[0]);
            __stcg(dst + 1, hv.u[1]);
        }

        // grid barrier (monotonic ticket; reset each replay by init_kernel)
        __syncthreads();
        if (tid == 0) {
            __threadfence();
            unsigned int tk = atomicAdd(&g_count, 1u);
            unsigned int target = (tk / 128u + 1u) * 128u;
            while (*(volatile unsigned int*)&g_count < target) { }
            __threadfence();
        }
        __syncthreads();
    }
}

// ======================= phase 3: head + softmax =======================
__global__ void __launch_bounds__(256) phase3_kernel(
    const float* __restrict__ Whq, const float* __restrict__ bq, float* __restrict__ out)
{
    int b = blockIdx.x;
    const __half* hf = g_hf16[0][0] + (size_t)b * Hsz;
    const __half* hb = g_hf16[1][0] + (size_t)b * Hsz;
    float part[10];
    #pragma unroll
    for (int q = 0; q < 10; q++) part[q] = 0.f;
    for (int k = threadIdx.x; k < Hsz; k += 256) {
        float hv = __half2float(hf[k]) + __half2float(hb[k]);
        #pragma unroll
        for (int q = 0; q < 10; q++) part[q] += hv * Whq[k * 10 + q];
    }
    #pragma unroll
    for (int q = 0; q < 10; q++)
        #pragma unroll
        for (int off = 16; off > 0; off >>= 1)
            part[q] += __shfl_xor_sync(0xffffffffu, part[q], off);
    __shared__ float red[8][10];
    int w = threadIdx.x >> 5, lane = threadIdx.x & 31;
    if (lane == 0)
        for (int q = 0; q < 10; q++) red[w][q] = part[q];
    __syncthreads();
    if (threadIdx.x == 0) {
        float lg[10]; float mx = -1e30f;
        for (int q = 0; q < 10; q++) {
            float v = bq[q];
            for (int w2 = 0; w2 < 8; w2++) v += red[w2][q];
            lg[q] = v;
            mx = fmaxf(mx, v);
        }
        float ssum = 0.f;
        for (int q = 0; q < 10; q++) { lg[q] = expf(lg[q] - mx); ssum += lg[q]; }
        float inv = 1.f / ssum;
        for (int q = 0; q < 10; q++) out[b * 10 + q] = lg[q] * inv;
    }
}

// ======================= launcher =======================
extern "C" void kernel_launch(void* const* d_in, const int* in_sizes, int n_in,
                              void* d_out, int out_size)
{
    const int*   inputs = (const int*)d_in[0];
    const float* emb = (const float*)d_in[1];
    const float* Wxf = (const float*)d_in[2];
    const float* Whf = (const float*)d_in[3];
    const float* bf  = (const float*)d_in[4];
    const float* Wxb = (const float*)d_in[5];
    const float* Whb = (const float*)d_in[6];
    const float* bb  = (const float*)d_in[7];
    const float* Whq = (const float*)d_in[8];
    const float* bq  = (const float*)d_in[9];
    float* out = (float*)d_out;

    static int attr_set = 0;
    if (!attr_set) {
        cudaFuncSetAttribute(phase1_mma_kernel,
                             cudaFuncAttributeMaxDynamicSharedMemorySize, P1_SMEM);
        cudaFuncSetAttribute(phase2_kernel,
                             cudaFuncAttributeMaxDynamicSharedMemorySize, P2_SMEM);
        attr_set = 1;
    }

    init_kernel<<<256, 256>>>();
    split_x_kernel<<<131072, 256>>>(inputs, emb);
    split_wx_kernel<<<16384, 256>>>(Wxf, Wxb);
    split_wh_kernel<<<32768, 256>>>(Whf, Whb);
    dim3 g1(128, 512);                               // 8192/64 n-tiles x 65536/128 m-tiles
    phase1_mma_kernel<<<g1, 256, P1_SMEM>>>();
    phase2_kernel<<<128, 256, P2_SMEM>>>(bf, bb);    // persistent, single wave
    phase3_kernel<<<256, 256>>>(Whq, bq, out);
}

// round 13
// speedup vs baseline: 5.4051x; 1.1562x over previous
#include <cuda_runtime.h>
#include <cuda_fp16.h>
#include <mma.h>
#include <math.h>
#include <stdint.h>

using namespace nvcuda;

#define Bsz 256
#define Ssz 256
#define Esz 512
#define Hsz 1024

// ======================= scratch =======================
__device__ __half g_Gf[(size_t)65536 * 4096];           // fwd gate pre-acts, fp16 (no bias)
__device__ __half g_Gb[(size_t)65536 * 4096];           // bwd gate pre-acts, fp16 (no bias)
__device__ __half g_hf16[2][2][Bsz * Hsz];              // [dir][buf] hidden, fp16
__device__ unsigned int g_count;                        // grid barrier
__device__ __half g_Xh[(size_t)65536 * 512];            // x fp16
__device__ __half g_Wxh[(size_t)512 * 8192];            // Wx fp16, [k][dir*4096+n]
__device__ __half g_Whh[(size_t)1024 * 8192];           // Wh fp16, [k][dir*4096+n]

// ======================= helpers =======================
__device__ __forceinline__ void cp_async16(void* sptr, const void* gptr) {
    uint32_t sa = (uint32_t)__cvta_generic_to_shared(sptr);
    asm volatile("cp.async.cg.shared.global [%0], [%1], 16;" :: "r"(sa), "l"(gptr) : "memory");
}
__device__ __forceinline__ void cp_commit() { asm volatile("cp.async.commit_group;" ::: "memory"); }
template <int N>
__device__ __forceinline__ void cp_wait() { asm volatile("cp.async.wait_group %0;" :: "n"(N) : "memory"); }

__device__ __forceinline__ float sigf(float x)   { return 1.f / (1.f + __expf(-x)); }
__device__ __forceinline__ float tanhf_(float x) { return 2.f / (1.f + __expf(-2.f * x)) - 1.f; }

// ======================= init =======================
__global__ void init_kernel() {
    size_t n = (size_t)2 * 2 * Bsz * Hsz;
    __half* p = &g_hf16[0][0][0];
    for (size_t i = (size_t)blockIdx.x * blockDim.x + threadIdx.x; i < n;
         i += (size_t)gridDim.x * blockDim.x)
        p[i] = __float2half(0.f);
    if (blockIdx.x == 0 && threadIdx.x == 0) g_count = 0u;
}

// ======================= split/prep kernels =======================
__global__ void __launch_bounds__(256) split_x_kernel(
    const int* __restrict__ inputs, const float* __restrict__ emb)
{
    size_t idx = (size_t)blockIdx.x * blockDim.x + threadIdx.x;
    if (idx >= (size_t)65536 * 512) return;
    int m = (int)(idx >> 9);
    int k = (int)(idx & 511);
    int b = m & 255, s = m >> 8;
    int tok = inputs[b * Ssz + s];
    g_Xh[idx] = __float2half(emb[(size_t)tok * Esz + k]);
}

__global__ void __launch_bounds__(256) split_wx_kernel(
    const float* __restrict__ Wxf, const float* __restrict__ Wxb)
{
    size_t idx = (size_t)blockIdx.x * blockDim.x + threadIdx.x;
    if (idx >= (size_t)512 * 8192) return;
    int k = (int)(idx >> 13);
    int c = (int)(idx & 8191);
    const float* W = (c >= 4096) ? Wxb : Wxf;
    g_Wxh[idx] = __float2half(W[(size_t)k * 4096 + (c & 4095)]);
}

__global__ void __launch_bounds__(256) split_wh_kernel(
    const float* __restrict__ Whf, const float* __restrict__ Whb)
{
    size_t idx = (size_t)blockIdx.x * blockDim.x + threadIdx.x;
    if (idx >= (size_t)1024 * 8192) return;
    int k = (int)(idx >> 13);
    int c = (int)(idx & 8191);
    const float* W = (c >= 4096) ? Whb : Whf;
    g_Whh[idx] = __float2half(W[(size_t)k * 4096 + (c & 4095)]);
}

// ======================= phase 1: WMMA GEMM =======================
// G[65536,8192] = X_fp16[65536,512] @ W_fp16[512,8192], G stored fp16
// CTA tile 128x64, K-chunks of 64, cp.async double-buffered.
// smem: A 2x[128][72] half (36864B, aliased as f32 staging [128][68]) | B 2x[64][72] (18432B)
#define P1_SMEM (36864 + 18432)

__global__ void __launch_bounds__(256) phase1_mma_kernel()
{
    extern __shared__ char sm[];
    __half* sA = (__half*)sm;                        // 2 x 128 x 72
    __half* sB = (__half*)(sm + 36864);              // 2 x 64 x 72
    float*  stg = (float*)sm;                        // staging [128][68] f32 (34816B)

    int tid = threadIdx.x;
    int wid = tid >> 5;
    int n0 = blockIdx.x * 64;       // global col in [0,8192)
    int m0 = blockIdx.y * 128;
    int wm = (wid & 3) * 32;
    int wn = (wid >> 2) * 32;

    wmma::fragment<wmma::accumulator, 16, 16, 16, float> acc[2][2];
    #pragma unroll
    for (int i = 0; i < 2; i++)
        #pragma unroll
        for (int j = 0; j < 2; j++) wmma::fill_fragment(acc[i][j], 0.f);

    auto prefetch = [&](int kc, int b) {
        __half* A = sA + b * 128 * 72;
        __half* B = sB + b * 64 * 72;
        #pragma unroll
        for (int i = 0; i < 4; i++) {                 // A: 1024 16B units
            int u = tid + i * 256;
            int row = u >> 3, seg = u & 7;
            cp_async16(A + row * 72 + seg * 8,
                       g_Xh + (size_t)(m0 + row) * 512 + kc * 64 + seg * 8);
        }
        #pragma unroll
        for (int i = 0; i < 2; i++) {                 // B: 512 units
            int u = tid + i * 256;
            int row = u >> 3, seg = u & 7;
            cp_async16(B + row * 72 + seg * 8,
                       g_Wxh + (size_t)(kc * 64 + row) * 8192 + n0 + seg * 8);
        }
        cp_commit();
    };

    prefetch(0, 0);
    for (int kc = 0; kc < 8; kc++) {
        int b = kc & 1;
        if (kc + 1 < 8) { prefetch(kc + 1, b ^ 1); cp_wait<1>(); }
        else cp_wait<0>();
        __syncthreads();
        __half* A = sA + b * 128 * 72;
        __half* B = sB + b * 64 * 72;
        #pragma unroll
        for (int kk = 0; kk < 4; kk++) {
            wmma::fragment<wmma::matrix_a, 16, 16, 16, __half, wmma::row_major> af[2];
            wmma::fragment<wmma::matrix_b, 16, 16, 16, __half, wmma::row_major> bf2[2];
            #pragma unroll
            for (int i = 0; i < 2; i++)
                wmma::load_matrix_sync(af[i], A + (wm + i * 16) * 72 + kk * 16, 72);
            #pragma unroll
            for (int j = 0; j < 2; j++)
                wmma::load_matrix_sync(bf2[j], B + kk * 16 * 72 + wn + j * 16, 72);
            #pragma unroll
            for (int i = 0; i < 2; i++)
                #pragma unroll
                for (int j = 0; j < 2; j++)
                    wmma::mma_sync(acc[i][j], af[i], bf2[j], acc[i][j]);
        }
        __syncthreads();
    }

    // epilogue: stage f32 accs to smem, convert to fp16, coalesced streaming stores
    #pragma unroll
    for (int i = 0; i < 2; i++)
        #pragma unroll
        for (int j = 0; j < 2; j++)
            wmma::store_matrix_sync(stg + (wm + i * 16) * 68 + wn + j * 16,
                                    acc[i][j], 68, wmma::mem_row_major);
    __syncthreads();

    int dir = n0 >> 12;
    int nl = n0 & 4095;
    __half* Gout = dir ? g_Gb : g_Gf;
    {
        int row = tid >> 1, c0 = (tid & 1) * 32;
        const float* srow = stg + row * 68 + c0;
        __half* orow = Gout + (size_t)(m0 + row) * 4096 + nl + c0;
        union { __half h[32]; uint4 u[4]; } ov;
        #pragma unroll
        for (int j = 0; j < 32; j++) ov.h[j] = __float2half(srow[j]);
        #pragma unroll
        for (int q = 0; q < 4; q++) __stcs((uint4*)orow + q, ov.u[q]);
    }
}

// ======================= phase 2: persistent WMMA recurrence =======================
// 128 CTAs x 256 thr. CTA ci: dir=ci>>6, h-cols [g0,g0+16), 64 gate-cols.
// Wh tile persistent in smem (loaded once); A (h) double-buffered per step.
// smem: A 2x[256][72] half = 73728 (aliased as f32 staging [256][68])
//       B [1024][72] half = 147456 @73728 -> total 221184
#define P2_SMEM (73728 + 147456)

__global__ void __launch_bounds__(256, 1) phase2_kernel(
    const float* __restrict__ bf_, const float* __restrict__ bb_)
{
    extern __shared__ char sm[];
    __half* sA = (__half*)sm;                         // 2 x 256 x 72
    __half* sB = (__half*)(sm + 73728);               // 1024 x 72 persistent
    float*  stg = (float*)sm;                         // staging [256][68]
    __shared__ float sBias[64];                       // c = e*16+j

    int ci  = blockIdx.x;
    int dir = ci >> 6;
    int g0  = (ci & 63) * 16;
    const __half* G = dir ? g_Gb : g_Gf;
    const float* bias = dir ? bb_ : bf_;

    int tid = threadIdx.x;
    int wid = tid >> 5;
    int wm = (wid & 3) * 64;        // 4 x 64 rows
    int wn = (wid >> 2) * 32;       // 2 x 32 cols

    if (tid < 64) sBias[tid] = bias[(tid >> 4) * 1024 + g0 + (tid & 15)];

    // ---- load Wh tile ONCE (persistent across all 256 steps) ----
    #pragma unroll 4
    for (int i = 0; i < 32; i++) {                    // 8192 16B units
        int u = tid + i * 256;
        int krow = u >> 3, seg = u & 7;
        int e = seg >> 1, h8 = seg & 1;
        cp_async16(sB + krow * 72 + e * 16 + h8 * 8,
                   g_Whh + (size_t)krow * 8192 + dir * 4096 + e * 1024 + g0 + h8 * 8);
    }
    cp_commit();

    float cst[16];
    #pragma unroll
    for (int j = 0; j < 16; j++) cst[j] = 0.f;

    cp_wait<0>();
    __syncthreads();

    for (int t = 0; t < Ssz; t++) {
        const __half* hin = g_hf16[dir][t & 1];
        __half*       hout = g_hf16[dir][(t + 1) & 1];
        int s = dir ? (Ssz - 1 - t) : t;

        // prefetch this thread's G row (streaming; consumed in epilogue)
        const __half* grow = G + ((size_t)(s * 256 + tid)) * 4096 + g0;
        union { uint4 u[8]; __half h[64]; } gv;
        #pragma unroll
        for (int g = 0; g < 4; g++) {
            gv.u[g * 2]     = __ldcs((const uint4*)(grow + g * 1024));
            gv.u[g * 2 + 1] = __ldcs((const uint4*)(grow + g * 1024 + 8));
        }

        wmma::fragment<wmma::accumulator, 16, 16, 16, float> acc[4][2];
        #pragma unroll
        for (int i = 0; i < 4; i++)
            #pragma unroll
            for (int j = 0; j < 2; j++) wmma::fill_fragment(acc[i][j], 0.f);

        auto prefetchA = [&](int kc, int b) {
            __half* A = sA + b * 256 * 72;
            #pragma unroll
            for (int i = 0; i < 8; i++) {             // A: 2048 units
                int u = tid + i * 256;
                int row = u >> 3, seg = u & 7;
                cp_async16(A + row * 72 + seg * 8,
                           hin + (size_t)row * 1024 + kc * 64 + seg * 8);
            }
            cp_commit();
        };

        prefetchA(0, 0);
        for (int kc = 0; kc < 16; kc++) {
            int b = kc & 1;
            if (kc + 1 < 16) { prefetchA(kc + 1, b ^ 1); cp_wait<1>(); }
            else cp_wait<0>();
            __syncthreads();
            __half* A = sA + b * 256 * 72;
            __half* B = sB + (kc * 64) * 72;
            #pragma unroll
            for (int kk = 0; kk < 4; kk++) {
                wmma::fragment<wmma::matrix_a, 16, 16, 16, __half, wmma::row_major> af[4];
                wmma::fragment<wmma::matrix_b, 16, 16, 16, __half, wmma::row_major> bf2[2];
                #pragma unroll
                for (int i = 0; i < 4; i++)
                    wmma::load_matrix_sync(af[i], A + (wm + i * 16) * 72 + kk * 16, 72);
                #pragma unroll
                for (int j = 0; j < 2; j++)
                    wmma::load_matrix_sync(bf2[j], B + kk * 16 * 72 + wn + j * 16, 72);
                #pragma unroll
                for (int i = 0; i < 4; i++)
                    #pragma unroll
                    for (int j = 0; j < 2; j++)
                        wmma::mma_sync(acc[i][j], af[i], bf2[j], acc[i][j]);
            }
            __syncthreads();
        }

        // stage accumulators to smem (f32, ld=68), aliases A buffers (synced above)
        #pragma unroll
        for (int i = 0; i < 4; i++)
            #pragma unroll
            for (int j = 0; j < 2; j++)
                wmma::store_matrix_sync(stg + (wm + i * 16) * 68 + wn + j * 16,
                                        acc[i][j], 68, wmma::mem_row_major);
        __syncthreads();

        // epilogue: thread tid owns batch-row tid, h-cols g0..g0+16
        {
            const float* srow = stg + tid * 68;
            union { __half h[16]; uint4 u[2]; } hv;
            #pragma unroll
            for (int j = 0; j < 16; j++) {
                float gi = srow[j]      + __half2float(gv.h[j])      + sBias[j];
                float gf = srow[16 + j] + __half2float(gv.h[16 + j]) + sBias[16 + j];
                float go = srow[32 + j] + __half2float(gv.h[32 + j]) + sBias[32 + j];
                float gc = srow[48 + j] + __half2float(gv.h[48 + j]) + sBias[48 + j];
                float cs = sigf(gf) * cst[j] + sigf(gi) * tanhf_(gc);
                cst[j] = cs;
                hv.h[j] = __float2half(sigf(go) * tanhf_(cs));
            }
            uint4* dst = (uint4*)(hout + (size_t)tid * 1024 + g0);
            __stcg(dst, hv.u[0]);
            __stcg(dst + 1, hv.u[1]);
        }

        // grid barrier (monotonic ticket; reset each replay by init_kernel)
        __syncthreads();
        if (tid == 0) {
            __threadfence();
            unsigned int tk = atomicAdd(&g_count, 1u);
            unsigned int target = (tk / 128u + 1u) * 128u;
            while (*(volatile unsigned int*)&g_count < target) { }
            __threadfence();
        }
        __syncthreads();
    }
}

// ======================= phase 3: head + softmax =======================
__global__ void __launch_bounds__(256) phase3_kernel(
    const float* __restrict__ Whq, const float* __restrict__ bq, float* __restrict__ out)
{
    int b = blockIdx.x;
    const __half* hf = g_hf16[0][0] + (size_t)b * Hsz;
    const __half* hb = g_hf16[1][0] + (size_t)b * Hsz;
    float part[10];
    #pragma unroll
    for (int q = 0; q < 10; q++) part[q] = 0.f;
    for (int k = threadIdx.x; k < Hsz; k += 256) {
        float hv = __half2float(hf[k]) + __half2float(hb[k]);
        #pragma unroll
        for (int q = 0; q < 10; q++) part[q] += hv * Whq[k * 10 + q];
    }
    #pragma unroll
    for (int q = 0; q < 10; q++)
        #pragma unroll
        for (int off = 16; off > 0; off >>= 1)
            part[q] += __shfl_xor_sync(0xffffffffu, part[q], off);
    __shared__ float red[8][10];
    int w = threadIdx.x >> 5, lane = threadIdx.x & 31;
    if (lane == 0)
        for (int q = 0; q < 10; q++) red[w][q] = part[q];
    __syncthreads();
    if (threadIdx.x == 0) {
        float lg[10]; float mx = -1e30f;
        for (int q = 0; q < 10; q++) {
            float v = bq[q];
            for (int w2 = 0; w2 < 8; w2++) v += red[w2][q];
            lg[q] = v;
            mx = fmaxf(mx, v);
        }
        float ssum = 0.f;
        for (int q = 0; q < 10; q++) { lg[q] = expf(lg[q] - mx); ssum += lg[q]; }
        float inv = 1.f / ssum;
        for (int q = 0; q < 10; q++) out[b * 10 + q] = lg[q] * inv;
    }
}

// ======================= launcher =======================
extern "C" void kernel_launch(void* const* d_in, const int* in_sizes, int n_in,
                              void* d_out, int out_size)
{
    const int*   inputs = (const int*)d_in[0];
    const float* emb = (const float*)d_in[1];
    const float* Wxf = (const float*)d_in[2];
    const float* Whf = (const float*)d_in[3];
    const float* bf  = (const float*)d_in[4];
    const float* Wxb = (const float*)d_in[5];
    const float* Whb = (const float*)d_in[6];
    const float* bb  = (const float*)d_in[7];
    const float* Whq = (const float*)d_in[8];
    const float* bq  = (const float*)d_in[9];
    float* out = (float*)d_out;

    static int attr_set = 0;
    if (!attr_set) {
        cudaFuncSetAttribute(phase1_mma_kernel,
                             cudaFuncAttributeMaxDynamicSharedMemorySize, P1_SMEM);
        cudaFuncSetAttribute(phase2_kernel,
                             cudaFuncAttributeMaxDynamicSharedMemorySize, P2_SMEM);
        attr_set = 1;
    }

    init_kernel<<<256, 256>>>();
    split_x_kernel<<<131072, 256>>>(inputs, emb);
    split_wx_kernel<<<16384, 256>>>(Wxf, Wxb);
    split_wh_kernel<<<32768, 256>>>(Whf, Whb);
    dim3 g1(128, 512);                               // 8192/64 n-tiles x 65536/128 m-tiles
    phase1_mma_kernel<<<g1, 256, P1_SMEM>>>();
    phase2_kernel<<<128, 256, P2_SMEM>>>(bf, bb);    // persistent, single wave
    phase3_kernel<<<256, 256>>>(Whq, bq, out);
}

// round 17
// speedup vs baseline: 5.5065x; 1.0188x over previous
#include <cuda_runtime.h>
#include <cuda_fp16.h>
#include <mma.h>
#include <math.h>
#include <stdint.h>

using namespace nvcuda;

#define Bsz 256
#define Ssz 256
#define Esz 512
#define Hsz 1024

// ======================= scratch =======================
__device__ __half g_Gf[(size_t)65536 * 4096];           // fwd gate pre-acts, fp16 (no bias)
__device__ __half g_Gb[(size_t)65536 * 4096];           // bwd gate pre-acts, fp16 (no bias)
__device__ __half g_hf16[2][2][Bsz * Hsz];              // [dir][buf] hidden, fp16
__device__ unsigned int g_count;                        // grid barrier
__device__ __half g_Xh[(size_t)65536 * 512];            // x fp16
__device__ __half g_Wxh[(size_t)512 * 8192];            // Wx fp16, [k][dir*4096+n]
__device__ __half g_Whh[(size_t)1024 * 8192];           // Wh fp16, [k][dir*4096+n]

// ======================= helpers =======================
__device__ __forceinline__ void cp_async16(void* sptr, const void* gptr) {
    uint32_t sa = (uint32_t)__cvta_generic_to_shared(sptr);
    asm volatile("cp.async.cg.shared.global [%0], [%1], 16;" :: "r"(sa), "l"(gptr) : "memory");
}
__device__ __forceinline__ void cp_commit() { asm volatile("cp.async.commit_group;" ::: "memory"); }
template <int N>
__device__ __forceinline__ void cp_wait() { asm volatile("cp.async.wait_group %0;" :: "n"(N) : "memory"); }

__device__ __forceinline__ float sigf(float x)   { return 1.f / (1.f + __expf(-x)); }
__device__ __forceinline__ float tanhf_(float x) { return 2.f / (1.f + __expf(-2.f * x)) - 1.f; }

// ======================= init =======================
__global__ void init_kernel() {
    size_t n = (size_t)2 * 2 * Bsz * Hsz;
    __half* p = &g_hf16[0][0][0];
    for (size_t i = (size_t)blockIdx.x * blockDim.x + threadIdx.x; i < n;
         i += (size_t)gridDim.x * blockDim.x)
        p[i] = __float2half(0.f);
    if (blockIdx.x == 0 && threadIdx.x == 0) g_count = 0u;
}

// ======================= split/prep kernels =======================
__global__ void __launch_bounds__(256) split_x_kernel(
    const int* __restrict__ inputs, const float* __restrict__ emb)
{
    size_t idx = (size_t)blockIdx.x * blockDim.x + threadIdx.x;
    if (idx >= (size_t)65536 * 512) return;
    int m = (int)(idx >> 9);
    int k = (int)(idx & 511);
    int b = m & 255, s = m >> 8;
    int tok = inputs[b * Ssz + s];
    g_Xh[idx] = __float2half(emb[(size_t)tok * Esz + k]);
}

__global__ void __launch_bounds__(256) split_wx_kernel(
    const float* __restrict__ Wxf, const float* __restrict__ Wxb)
{
    size_t idx = (size_t)blockIdx.x * blockDim.x + threadIdx.x;
    if (idx >= (size_t)512 * 8192) return;
    int k = (int)(idx >> 13);
    int c = (int)(idx & 8191);
    const float* W = (c >= 4096) ? Wxb : Wxf;
    g_Wxh[idx] = __float2half(W[(size_t)k * 4096 + (c & 4095)]);
}

__global__ void __launch_bounds__(256) split_wh_kernel(
    const float* __restrict__ Whf, const float* __restrict__ Whb)
{
    size_t idx = (size_t)blockIdx.x * blockDim.x + threadIdx.x;
    if (idx >= (size_t)1024 * 8192) return;
    int k = (int)(idx >> 13);
    int c = (int)(idx & 8191);
    const float* W = (c >= 4096) ? Whb : Whf;
    g_Whh[idx] = __float2half(W[(size_t)k * 4096 + (c & 4095)]);
}

// ======================= phase 1: WMMA GEMM =======================
// G[65536,8192] = X_fp16[65536,512] @ W_fp16[512,8192], G stored fp16
// CTA tile 128x128, K-chunks of 64, cp.async double-buffered, single sync/chunk.
// smem: A 2x[128][72] half (36864B) | B 2x[64][136] half (34816B)
//       staging aliases full smem: f32 [128][132] = 67584B
#define P1_SMEM (36864 + 34816)

__global__ void __launch_bounds__(256) phase1_mma_kernel()
{
    extern __shared__ char sm[];
    __half* sA = (__half*)sm;                        // 2 x 128 x 72
    __half* sB = (__half*)(sm + 36864);              // 2 x 64 x 136
    float*  stg = (float*)sm;                        // staging [128][132] f32

    int tid = threadIdx.x;
    int wid = tid >> 5;
    int n0 = blockIdx.x * 128;      // global col in [0,8192)
    int m0 = blockIdx.y * 128;
    int wm = (wid & 3) * 32;
    int wn = (wid >> 2) * 64;

    wmma::fragment<wmma::accumulator, 16, 16, 16, float> acc[2][4];
    #pragma unroll
    for (int i = 0; i < 2; i++)
        #pragma unroll
        for (int j = 0; j < 4; j++) wmma::fill_fragment(acc[i][j], 0.f);

    auto prefetch = [&](int kc, int b) {
        __half* A = sA + b * 128 * 72;
        __half* B = sB + b * 64 * 136;
        #pragma unroll
        for (int i = 0; i < 4; i++) {                 // A: 1024 16B units
            int u = tid + i * 256;
            int row = u >> 3, seg = u & 7;
            cp_async16(A + row * 72 + seg * 8,
                       g_Xh + (size_t)(m0 + row) * 512 + kc * 64 + seg * 8);
        }
        #pragma unroll
        for (int i = 0; i < 4; i++) {                 // B: 1024 16B units
            int u = tid + i * 256;
            int row = u >> 4, seg = u & 15;
            cp_async16(B + row * 136 + seg * 8,
                       g_Wxh + (size_t)(kc * 64 + row) * 8192 + n0 + seg * 8);
        }
        cp_commit();
    };

    prefetch(0, 0);
    for (int kc = 0; kc < 8; kc++) {
        int b = kc & 1;
        cp_wait<0>();
        __syncthreads();
        if (kc + 1 < 8) prefetch(kc + 1, b ^ 1);
        __half* A = sA + b * 128 * 72;
        __half* B = sB + b * 64 * 136;
        #pragma unroll
        for (int kk = 0; kk < 4; kk++) {
            wmma::fragment<wmma::matrix_a, 16, 16, 16, __half, wmma::row_major> af[2];
            wmma::fragment<wmma::matrix_b, 16, 16, 16, __half, wmma::row_major> bf2[4];
            #pragma unroll
            for (int i = 0; i < 2; i++)
                wmma::load_matrix_sync(af[i], A + (wm + i * 16) * 72 + kk * 16, 72);
            #pragma unroll
            for (int j = 0; j < 4; j++)
                wmma::load_matrix_sync(bf2[j], B + kk * 16 * 136 + wn + j * 16, 136);
            #pragma unroll
            for (int i = 0; i < 2; i++)
                #pragma unroll
                for (int j = 0; j < 4; j++)
                    wmma::mma_sync(acc[i][j], af[i], bf2[j], acc[i][j]);
        }
    }
    __syncthreads();

    // epilogue: stage f32 accs to smem, convert to fp16, coalesced streaming stores
    #pragma unroll
    for (int i = 0; i < 2; i++)
        #pragma unroll
        for (int j = 0; j < 4; j++)
            wmma::store_matrix_sync(stg + (wm + i * 16) * 132 + wn + j * 16,
                                    acc[i][j], 132, wmma::mem_row_major);
    __syncthreads();

    int dir = n0 >> 12;
    int nl = n0 & 4095;
    __half* Gout = dir ? g_Gb : g_Gf;
    {
        int row = tid >> 1, c0 = (tid & 1) * 64;
        const float* srow = stg + row * 132 + c0;
        __half* orow = Gout + (size_t)(m0 + row) * 4096 + nl + c0;
        union { __half h[64]; uint4 u[8]; } ov;
        #pragma unroll
        for (int j = 0; j < 64; j++) ov.h[j] = __float2half(srow[j]);
        #pragma unroll
        for (int q = 0; q < 8; q++) __stcs((uint4*)orow + q, ov.u[q]);
    }
}

// ======================= phase 2: persistent WMMA recurrence =======================
// 128 CTAs x 256 thr. CTA ci: dir=ci>>6, h-cols [g0,g0+16), 64 gate-cols.
// Wh tile persistent in smem (loaded once); A (h) double-buffered, single sync/chunk.
// G prefetched one step ahead (issued pre-barrier, consumed next epilogue).
// smem: A 2x[256][72] half = 73728 (aliased as f32 staging [256][68])
//       B [1024][72] half = 147456 @73728 -> total 221184
#define P2_SMEM (73728 + 147456)

__global__ void __launch_bounds__(256, 1) phase2_kernel(
    const float* __restrict__ bf_, const float* __restrict__ bb_)
{
    extern __shared__ char sm[];
    __half* sA = (__half*)sm;                         // 2 x 256 x 72
    __half* sB = (__half*)(sm + 73728);               // 1024 x 72 persistent
    float*  stg = (float*)sm;                         // staging [256][68]
    __shared__ float sBias[64];                       // c = e*16+j

    int ci  = blockIdx.x;
    int dir = ci >> 6;
    int g0  = (ci & 63) * 16;
    const __half* G = dir ? g_Gb : g_Gf;
    const float* bias = dir ? bb_ : bf_;

    int tid = threadIdx.x;
    int wid = tid >> 5;
    int wm = (wid & 3) * 64;        // 4 x 64 rows
    int wn = (wid >> 2) * 32;       // 2 x 32 cols

    if (tid < 64) sBias[tid] = bias[(tid >> 4) * 1024 + g0 + (tid & 15)];

    // ---- load Wh tile ONCE (persistent across all 256 steps) ----
    #pragma unroll 4
    for (int i = 0; i < 32; i++) {                    // 8192 16B units
        int u = tid + i * 256;
        int krow = u >> 3, seg = u & 7;
        int e = seg >> 1, h8 = seg & 1;
        cp_async16(sB + krow * 72 + e * 16 + h8 * 8,
                   g_Whh + (size_t)krow * 8192 + dir * 4096 + e * 1024 + g0 + h8 * 8);
    }
    cp_commit();

    float cst[16];
    #pragma unroll
    for (int j = 0; j < 16; j++) cst[j] = 0.f;

    // G prefetch buffer (one step ahead); load step 0 now
    union { uint4 u[8]; __half h[64]; } gv;
    {
        int s0 = dir ? (Ssz - 1) : 0;
        const __half* grow = G + ((size_t)(s0 * 256 + tid)) * 4096 + g0;
        #pragma unroll
        for (int g = 0; g < 4; g++) {
            gv.u[g * 2]     = __ldcs((const uint4*)(grow + g * 1024));
            gv.u[g * 2 + 1] = __ldcs((const uint4*)(grow + g * 1024 + 8));
        }
    }

    cp_wait<0>();
    __syncthreads();

    for (int t = 0; t < Ssz; t++) {
        const __half* hin = g_hf16[dir][t & 1];
        __half*       hout = g_hf16[dir][(t + 1) & 1];

        wmma::fragment<wmma::accumulator, 16, 16, 16, float> acc[4][2];
        #pragma unroll
        for (int i = 0; i < 4; i++)
            #pragma unroll
            for (int j = 0; j < 2; j++) wmma::fill_fragment(acc[i][j], 0.f);

        auto prefetchA = [&](int kc, int b) {
            __half* A = sA + b * 256 * 72;
            #pragma unroll
            for (int i = 0; i < 8; i++) {             // A: 2048 units
                int u = tid + i * 256;
                int row = u >> 3, seg = u & 7;
                cp_async16(A + row * 72 + seg * 8,
                           hin + (size_t)row * 1024 + kc * 64 + seg * 8);
            }
            cp_commit();
        };

        prefetchA(0, 0);
        for (int kc = 0; kc < 16; kc++) {
            int b = kc & 1;
            cp_wait<0>();
            __syncthreads();
            if (kc + 1 < 16) prefetchA(kc + 1, b ^ 1);
            __half* A = sA + b * 256 * 72;
            __half* B = sB + (kc * 64) * 72;
            #pragma unroll
            for (int kk = 0; kk < 4; kk++) {
                wmma::fragment<wmma::matrix_a, 16, 16, 16, __half, wmma::row_major> af[4];
                wmma::fragment<wmma::matrix_b, 16, 16, 16, __half, wmma::row_major> bf2[2];
                #pragma unroll
                for (int i = 0; i < 4; i++)
                    wmma::load_matrix_sync(af[i], A + (wm + i * 16) * 72 + kk * 16, 72);
                #pragma unroll
                for (int j = 0; j < 2; j++)
                    wmma::load_matrix_sync(bf2[j], B + kk * 16 * 72 + wn + j * 16, 72);
                #pragma unroll
                for (int i = 0; i < 4; i++)
                    #pragma unroll
                    for (int j = 0; j < 2; j++)
                        wmma::mma_sync(acc[i][j], af[i], bf2[j], acc[i][j]);
            }
        }
        __syncthreads();   // protect staging alias of A buffers

        // stage accumulators to smem (f32, ld=68)
        #pragma unroll
        for (int i = 0; i < 4; i++)
            #pragma unroll
            for (int j = 0; j < 2; j++)
                wmma::store_matrix_sync(stg + (wm + i * 16) * 68 + wn + j * 16,
                                        acc[i][j], 68, wmma::mem_row_major);
        __syncthreads();

        // epilogue: thread tid owns batch-row tid, h-cols g0..g0+16
        {
            const float* srow = stg + tid * 68;
            union { __half h[16]; uint4 u[2]; } hv;
            #pragma unroll
            for (int j = 0; j < 16; j++) {
                float gi = srow[j]      + __half2float(gv.h[j])      + sBias[j];
                float gf = srow[16 + j] + __half2float(gv.h[16 + j]) + sBias[16 + j];
                float go = srow[32 + j] + __half2float(gv.h[32 + j]) + sBias[32 + j];
                float gc = srow[48 + j] + __half2float(gv.h[48 + j]) + sBias[48 + j];
                float cs = sigf(gf) * cst[j] + sigf(gi) * tanhf_(gc);
                cst[j] = cs;
                hv.h[j] = __float2half(sigf(go) * tanhf_(cs));
            }
            uint4* dst = (uint4*)(hout + (size_t)tid * 1024 + g0);
            __stcg(dst, hv.u[0]);
            __stcg(dst + 1, hv.u[1]);
        }

        // prefetch next step's G rows (read-only; latency hidden behind barrier+MMA)
        if (t + 1 < Ssz) {
            int s2 = dir ? (Ssz - 2 - t) : (t + 1);
            const __half* grow = G + ((size_t)(s2 * 256 + tid)) * 4096 + g0;
            #pragma unroll
            for (int g = 0; g < 4; g++) {
                gv.u[g * 2]     = __ldcs((const uint4*)(grow + g * 1024));
                gv.u[g * 2 + 1] = __ldcs((const uint4*)(grow + g * 1024 + 8));
            }
        }

        // grid barrier (monotonic ticket; reset each replay by init_kernel)
        __syncthreads();
        if (tid == 0) {
            __threadfence();
            unsigned int tk = atomicAdd(&g_count, 1u);
            unsigned int target = (tk / 128u + 1u) * 128u;
            while (*(volatile unsigned int*)&g_count < target) { }
            __threadfence();
        }
        __syncthreads();
    }
}

// ======================= phase 3: head + softmax =======================
__global__ void __launch_bounds__(256) phase3_kernel(
    const float* __restrict__ Whq, const float* __restrict__ bq, float* __restrict__ out)
{
    int b = blockIdx.x;
    const __half* hf = g_hf16[0][0] + (size_t)b * Hsz;
    const __half* hb = g_hf16[1][0] + (size_t)b * Hsz;
    float part[10];
    #pragma unroll
    for (int q = 0; q < 10; q++) part[q] = 0.f;
    for (int k = threadIdx.x; k < Hsz; k += 256) {
        float hv = __half2float(hf[k]) + __half2float(hb[k]);
        #pragma unroll
        for (int q = 0; q < 10; q++) part[q] += hv * Whq[k * 10 + q];
    }
    #pragma unroll
    for (int q = 0; q < 10; q++)
        #pragma unroll
        for (int off = 16; off > 0; off >>= 1)
            part[q] += __shfl_xor_sync(0xffffffffu, part[q], off);
    __shared__ float red[8][10];
    int w = threadIdx.x >> 5, lane = threadIdx.x & 31;
    if (lane == 0)
        for (int q = 0; q < 10; q++) red[w][q] = part[q];
    __syncthreads();
    if (threadIdx.x == 0) {
        float lg[10]; float mx = -1e30f;
        for (int q = 0; q < 10; q++) {
            float v = bq[q];
            for (int w2 = 0; w2 < 8; w2++) v += red[w2][q];
            lg[q] = v;
            mx = fmaxf(mx, v);
        }
        float ssum = 0.f;
        for (int q = 0; q < 10; q++) { lg[q] = expf(lg[q] - mx); ssum += lg[q]; }
        float inv = 1.f / ssum;
        for (int q = 0; q < 10; q++) out[b * 10 + q] = lg[q] * inv;
    }
}

// ======================= launcher =======================
extern "C" void kernel_launch(void* const* d_in, const int* in_sizes, int n_in,
                              void* d_out, int out_size)
{
    const int*   inputs = (const int*)d_in[0];
    const float* emb = (const float*)d_in[1];
    const float* Wxf = (const float*)d_in[2];
    const float* Whf = (const float*)d_in[3];
    const float* bf  = (const float*)d_in[4];
    const float* Wxb = (const float*)d_in[5];
    const float* Whb = (const float*)d_in[6];
    const float* bb  = (const float*)d_in[7];
    const float* Whq = (const float*)d_in[8];
    const float* bq  = (const float*)d_in[9];
    float* out = (float*)d_out;

    static int attr_set = 0;
    if (!attr_set) {
        cudaFuncSetAttribute(phase1_mma_kernel,
                             cudaFuncAttributeMaxDynamicSharedMemorySize, P1_SMEM);
        cudaFuncSetAttribute(phase2_kernel,
                             cudaFuncAttributeMaxDynamicSharedMemorySize, P2_SMEM);
        attr_set = 1;
    }

    init_kernel<<<256, 256>>>();
    split_x_kernel<<<131072, 256>>>(inputs, emb);
    split_wx_kernel<<<16384, 256>>>(Wxf, Wxb);
    split_wh_kernel<<<32768, 256>>>(Whf, Whb);
    dim3 g1(64, 512);                                // 8192/128 n-tiles x 65536/128 m-tiles
    phase1_mma_kernel<<<g1, 256, P1_SMEM>>>();
    phase2_kernel<<<128, 256, P2_SMEM>>>(bf, bb);    // persistent, single wave
    phase3_kernel<<<256, 256>>>(Whq, bq, out);
}